// round 1
// baseline (speedup 1.0000x reference)
#include <cuda_runtime.h>

// Problem constants
#define BB   4096
#define TT   50
#define OBS  64
#define ACTD 16
#define DIN  80      // OBS + ACT
#define HH   256
#define G4   1024    // 4*H
#define NL   5
#define OUTD 64

// Kernel config
#define RPB  32            // batch rows per CTA
#define NCTA (BB / RPB)    // 128
#define NTH  256
#define KP   40            // k-panel depth
#define SAS  36            // sA row stride in floats (16B-aligned, low-conflict)
#define KPAD 360           // padded K (9 panels of 40; covers 336 real + 24 zero)

// Shared memory layout (in floats)
#define SZ_SA   (KPAD * SAS)     // 12960  A operand, k-major transposed [k][row]
#define SZ_SW   (2 * KP * 256)   // 20480  double-buffered weight panels
#define SZ_SC   (RPB * 257)      // 8224   cell state [row][hk], padded stride
#define SZ_SHN  (HH * SAS)       // 9216   staging for new h / MLP activations
#define SZ_SB   (G4)             // 1024   bh cache
#define OFF_SA  0
#define OFF_SW  (OFF_SA + SZ_SA)
#define OFF_SC  (OFF_SW + SZ_SW)
#define OFF_SHN (OFF_SC + SZ_SC)
#define OFF_SB  (OFF_SHN + SZ_SHN)
#define SMEM_FLOATS (OFF_SB + SZ_SB)   // 51904 floats = 207616 bytes

__device__ __forceinline__ float sigf(float x) {
    return __fdividef(1.0f, 1.0f + __expf(-x));
}

// Load one LSTM weight panel: rows [kbase, kbase+KP) of [Wi; Wh], columns
// restricted to this pass's 64 hidden cols replicated across 4 gates.
// sW panel layout: [kk][g*64 + hk_local]. Zero-pads k >= 336.
__device__ __forceinline__ void load_lstm_panel(
    float* __restrict__ dst, const float* __restrict__ Wi,
    const float* __restrict__ Wh, int kbase, int pass, int tid)
{
    #pragma unroll 4
    for (int i = tid; i < KP * 256; i += NTH) {
        const int kk  = i >> 8;
        const int cl  = i & 255;
        const int k   = kbase + kk;
        const int g   = cl >> 6;
        const int hkl = cl & 63;
        const int j   = g * HH + (pass << 6) + hkl;
        float v = 0.0f;
        if (k < DIN)            v = Wi[k * G4 + j];
        else if (k < DIN + HH)  v = Wh[(k - DIN) * G4 + j];
        dst[i] = v;   // i == kk*256 + cl
    }
}

// MLP hidden-layer panel: rows [kbase, kbase+KP) of W_l [256x256], all 256 cols.
__device__ __forceinline__ void load_mlp_panel(
    float* __restrict__ dst, const float* __restrict__ Wl, int kbase, int tid)
{
    #pragma unroll 4
    for (int i = tid; i < KP * 256; i += NTH) {
        const int kk = i >> 8;
        const int c  = i & 255;
        const int k  = kbase + kk;
        dst[i] = (k < HH) ? Wl[k * HH + c] : 0.0f;
    }
}

// Output-layer panel: rows [kbase, kbase+KP) of Wout [256x64].
__device__ __forceinline__ void load_out_panel(
    float* __restrict__ dst, const float* __restrict__ Wout, int kbase, int tid)
{
    #pragma unroll 2
    for (int i = tid; i < KP * 64; i += NTH) {
        const int kk = i >> 6;
        const int c  = i & 63;
        const int k  = kbase + kk;
        dst[i] = (k < HH) ? Wout[k * OUTD + c] : 0.0f;
    }
}

__global__ void __launch_bounds__(NTH, 1)
lstm_fwd_kernel(const float* __restrict__ traj, const float* __restrict__ act,
                const float* __restrict__ Wi,   const float* __restrict__ Wh,
                const float* __restrict__ bh,   const float* __restrict__ mlpW,
                const float* __restrict__ mlpB, const float* __restrict__ Wout,
                const float* __restrict__ bout, float* __restrict__ out)
{
    extern __shared__ float sm[];
    float* sA  = sm + OFF_SA;    // [KPAD][SAS]   (k-major, rows 0..79 = x, 80..335 = h)
    float* sW  = sm + OFF_SW;    // [2][KP][256]
    float* sC  = sm + OFF_SC;    // [RPB][257]
    float* sHN = sm + OFF_SHN;   // [HH][SAS]
    float* sB  = sm + OFF_SB;    // [G4]

    const int tid  = threadIdx.x;
    const int row0 = blockIdx.x * RPB;
    const int rgrp = tid & 7;        // 8 row groups of 4 rows
    const int cgrp = tid >> 3;       // 32 column groups
    const int r0   = rgrp << 2;

    // ---- init: zero h-region of sA (incl. zero-pad rows), zero cell state, cache bh
    for (int i = tid; i < (KPAD - DIN) * SAS; i += NTH) sA[DIN * SAS + i] = 0.0f;
    for (int i = tid; i < SZ_SC; i += NTH) sC[i] = 0.0f;
    for (int i = tid; i < G4;    i += NTH) sB[i] = bh[i];
    __syncthreads();

    // ============================ LSTM over time ============================
    for (int t = 0; t < TT; ++t) {
        // load x_t (transposed) into sA rows 0..79
        for (int i = tid; i < DIN * RPB; i += NTH) {
            const int r = i & 31;
            const int k = i >> 5;
            const int row = row0 + r;
            float v;
            if (k < OBS) v = traj[((size_t)row * TT + t) * OBS + k];
            else         v = act [((size_t)row * TT + t) * ACTD + (k - OBS)];
            sA[k * SAS + r] = v;
        }
        __syncthreads();

        // 4 passes over hidden dim (64 hidden cols x 4 gates per pass)
        for (int pass = 0; pass < 4; ++pass) {
            float acc[32];
            #pragma unroll
            for (int i = 0; i < 32; ++i) acc[i] = 0.0f;

            const int NP = KPAD / KP;   // 9 panels
            load_lstm_panel(sW, Wi, Wh, 0, pass, tid);
            __syncthreads();
            int buf = 0;
            for (int pi = 0; pi < NP; ++pi) {
                if (pi + 1 < NP)
                    load_lstm_panel(sW + (buf ^ 1) * (KP * 256), Wi, Wh,
                                    (pi + 1) * KP, pass, tid);
                const float* wp = sW + buf * (KP * 256);
                const int kbase = pi * KP;
                #pragma unroll 4
                for (int kk = 0; kk < KP; ++kk) {
                    const float4 a = *(const float4*)(sA + (kbase + kk) * SAS + r0);
                    const float* wr = wp + kk * 256 + (cgrp << 1);
                    #pragma unroll
                    for (int g = 0; g < 4; ++g) {
                        const float2 w = *(const float2*)(wr + g * 64);
                        acc[(g * 2 + 0) * 4 + 0] += w.x * a.x;
                        acc[(g * 2 + 0) * 4 + 1] += w.x * a.y;
                        acc[(g * 2 + 0) * 4 + 2] += w.x * a.z;
                        acc[(g * 2 + 0) * 4 + 3] += w.x * a.w;
                        acc[(g * 2 + 1) * 4 + 0] += w.y * a.x;
                        acc[(g * 2 + 1) * 4 + 1] += w.y * a.y;
                        acc[(g * 2 + 1) * 4 + 2] += w.y * a.z;
                        acc[(g * 2 + 1) * 4 + 3] += w.y * a.w;
                    }
                }
                __syncthreads();
                buf ^= 1;
            }

            // fused gate math: this thread exclusively owns (row, hk) pairs
            #pragma unroll
            for (int c = 0; c < 2; ++c) {
                const int hk = (pass << 6) + (cgrp << 1) + c;
                #pragma unroll
                for (int r = 0; r < 4; ++r) {
                    const int row = r0 + r;
                    const float zi = acc[(0 * 2 + c) * 4 + r] + sB[hk];
                    const float zf = acc[(1 * 2 + c) * 4 + r] + sB[256 + hk];
                    const float zg = acc[(2 * 2 + c) * 4 + r] + sB[512 + hk];
                    const float zo = acc[(3 * 2 + c) * 4 + r] + sB[768 + hk];
                    const float ig = sigf(zi);
                    const float fg = sigf(zf);
                    const float gg = zg * sigf(zg);        // silu
                    const float og = sigf(zo);
                    const float cn = fg * sC[row * 257 + hk] + ig * gg;
                    sC[row * 257 + hk] = cn;
                    sHN[hk * SAS + row] = og * cn * sigf(cn);  // o * silu(c_new)
                }
            }
        }
        __syncthreads();
        // commit h_new -> sA rows 80..335
        for (int i = tid; i < HH * RPB; i += NTH) {
            const int c = i >> 5, r = i & 31;
            sA[(DIN + c) * SAS + r] = sHN[c * SAS + r];
        }
        __syncthreads();
    }

    // ============================ MLP head ============================
    const int NP2 = 7;  // ceil(256/40), zero-padded tail
    for (int l = 0; l < NL; ++l) {
        float acc[32];
        #pragma unroll
        for (int i = 0; i < 32; ++i) acc[i] = 0.0f;

        const float* Wl = mlpW + (size_t)l * HH * HH;
        load_mlp_panel(sW, Wl, 0, tid);
        __syncthreads();
        int buf = 0;
        for (int pi = 0; pi < NP2; ++pi) {
            if (pi + 1 < NP2)
                load_mlp_panel(sW + (buf ^ 1) * (KP * 256), Wl, (pi + 1) * KP, tid);
            const float* wp = sW + buf * (KP * 256);
            const int kbase = pi * KP;
            #pragma unroll 4
            for (int kk = 0; kk < KP; ++kk) {
                const float4 a = *(const float4*)(sA + (DIN + kbase + kk) * SAS + r0);
                const float* wr = wp + kk * 256 + (cgrp << 3);
                const float4 w0 = *(const float4*)(wr);
                const float4 w1 = *(const float4*)(wr + 4);
                acc[ 0] += w0.x * a.x;  acc[ 1] += w0.x * a.y;  acc[ 2] += w0.x * a.z;  acc[ 3] += w0.x * a.w;
                acc[ 4] += w0.y * a.x;  acc[ 5] += w0.y * a.y;  acc[ 6] += w0.y * a.z;  acc[ 7] += w0.y * a.w;
                acc[ 8] += w0.z * a.x;  acc[ 9] += w0.z * a.y;  acc[10] += w0.z * a.z;  acc[11] += w0.z * a.w;
                acc[12] += w0.w * a.x;  acc[13] += w0.w * a.y;  acc[14] += w0.w * a.z;  acc[15] += w0.w * a.w;
                acc[16] += w1.x * a.x;  acc[17] += w1.x * a.y;  acc[18] += w1.x * a.z;  acc[19] += w1.x * a.w;
                acc[20] += w1.y * a.x;  acc[21] += w1.y * a.y;  acc[22] += w1.y * a.z;  acc[23] += w1.y * a.w;
                acc[24] += w1.z * a.x;  acc[25] += w1.z * a.y;  acc[26] += w1.z * a.z;  acc[27] += w1.z * a.w;
                acc[28] += w1.w * a.x;  acc[29] += w1.w * a.y;  acc[30] += w1.w * a.z;  acc[31] += w1.w * a.w;
            }
            __syncthreads();
            buf ^= 1;
        }
        // silu epilogue -> sHN (transposed), then commit to sA
        #pragma unroll
        for (int cc = 0; cc < 8; ++cc) {
            const int c = (cgrp << 3) + cc;
            const float b = mlpB[l * HH + c];
            #pragma unroll
            for (int r = 0; r < 4; ++r) {
                float v = acc[cc * 4 + r] + b;
                sHN[c * SAS + r0 + r] = v * sigf(v);
            }
        }
        __syncthreads();
        for (int i = tid; i < HH * RPB; i += NTH) {
            const int c = i >> 5, r = i & 31;
            sA[(DIN + c) * SAS + r] = sHN[c * SAS + r];
        }
        __syncthreads();
    }

    // ---- output layer: [32x256] @ [256x64] + bout
    {
        float acc[8];
        #pragma unroll
        for (int i = 0; i < 8; ++i) acc[i] = 0.0f;

        load_out_panel(sW, Wout, 0, tid);
        __syncthreads();
        int buf = 0;
        for (int pi = 0; pi < NP2; ++pi) {
            if (pi + 1 < NP2)
                load_out_panel(sW + (buf ^ 1) * (KP * 256), Wout, (pi + 1) * KP, tid);
            const float* wp = sW + buf * (KP * 256);
            const int kbase = pi * KP;
            #pragma unroll 4
            for (int kk = 0; kk < KP; ++kk) {
                const float4 a = *(const float4*)(sA + (DIN + kbase + kk) * SAS + r0);
                const float2 w = *(const float2*)(wp + kk * 64 + (cgrp << 1));
                acc[0] += w.x * a.x;  acc[1] += w.x * a.y;
                acc[2] += w.x * a.z;  acc[3] += w.x * a.w;
                acc[4] += w.y * a.x;  acc[5] += w.y * a.y;
                acc[6] += w.y * a.z;  acc[7] += w.y * a.w;
            }
            __syncthreads();
            buf ^= 1;
        }
        #pragma unroll
        for (int c2 = 0; c2 < 2; ++c2) {
            const int c = (cgrp << 1) + c2;
            const float b = bout[c];
            #pragma unroll
            for (int r = 0; r < 4; ++r) {
                out[(size_t)(row0 + r0 + r) * OUTD + c] = acc[c2 * 4 + r] + b;
            }
        }
    }
}

extern "C" void kernel_launch(void* const* d_in, const int* in_sizes, int n_in,
                              void* d_out, int out_size)
{
    const float* traj = (const float*)d_in[0];
    const float* act  = (const float*)d_in[1];
    const float* Wi   = (const float*)d_in[2];
    const float* Wh   = (const float*)d_in[3];
    const float* bh   = (const float*)d_in[4];
    const float* mlpW = (const float*)d_in[5];
    const float* mlpB = (const float*)d_in[6];
    const float* Wout = (const float*)d_in[7];
    const float* bout = (const float*)d_in[8];
    float* out = (float*)d_out;

    cudaFuncSetAttribute(lstm_fwd_kernel,
                         cudaFuncAttributeMaxDynamicSharedMemorySize,
                         SMEM_FLOATS * (int)sizeof(float));
    lstm_fwd_kernel<<<NCTA, NTH, SMEM_FLOATS * sizeof(float)>>>(
        traj, act, Wi, Wh, bh, mlpW, mlpB, Wout, bout, out);
}

// round 2
// speedup vs baseline: 3.1602x; 3.1602x over previous
#include <cuda_runtime.h>

// Problem constants
#define BB   4096
#define TT   50
#define OBS  64
#define ACTD 16
#define DIN  80      // OBS + ACT
#define HH   256
#define G4   1024    // 4*H
#define NL   5
#define OUTD 64

// Kernel config
#define RPB  32            // batch rows per CTA
#define NCTA (BB / RPB)    // 128
#define NTH  256
#define KP   56            // k-panel depth (336 = 6*56 exact)
#define NP_LSTM 6
#define NP_MLP  5          // ceil(256/56), zero-padded tail
#define SAS  36            // sA row stride in floats
#define AROWS 360          // 80 + 5*56 (MLP reads padded rows 336..359 = 0)

// Shared memory layout (floats)
#define SZ_SA   (AROWS * SAS)    // 12960
#define SZ_SW   (2 * KP * 256)   // 28672 double-buffered weight panels
#define SZ_SHN  (HH * SAS)       //  9216 staging for new h / MLP activations
#define SZ_SB   (G4)             //  1024 bh cache
#define OFF_SA  0
#define OFF_SW  (OFF_SA + SZ_SA)
#define OFF_SHN (OFF_SW + SZ_SW)
#define OFF_SB  (OFF_SHN + SZ_SHN)
#define SMEM_FLOATS (OFF_SB + SZ_SB)   // 51872 floats = 207488 B (< 227KB)

typedef unsigned long long ull;

__device__ __forceinline__ float sigf(float x) {
    return __fdividef(1.0f, 1.0f + __expf(-x));
}

// packed f32x2 helpers (sm_103a FFMA2 path — ptxas won't emit from C++)
__device__ __forceinline__ void ffma2(ull &d, ull a, ull b) {
    asm("fma.rn.f32x2 %0, %1, %2, %0;" : "+l"(d) : "l"(a), "l"(b));
}
__device__ __forceinline__ ull pk2(float lo, float hi) {
    ull r; asm("mov.b64 %0, {%1, %2};" : "=l"(r) : "f"(lo), "f"(hi)); return r;
}
__device__ __forceinline__ void upk2(ull v, float &lo, float &hi) {
    asm("mov.b64 {%0, %1}, %2;" : "=f"(lo), "=f"(hi) : "l"(v));
}

// LSTM weight panel: rows [kbase, kbase+56) of [Wi;Wh], this pass's 64 hidden
// cols replicated across 4 gates. dst[kk][g*64 + hkl]. All float4.
__device__ __forceinline__ void load_lstm_panel(
    float* __restrict__ dst, const float* __restrict__ Wi,
    const float* __restrict__ Wh, int kbase, int pass, int tid)
{
    #pragma unroll 2
    for (int it = 0; it < 14; ++it) {          // 3584 float4 / 256 threads
        const int f   = tid + it * NTH;
        const int kk  = f >> 6;
        const int rem = f & 63;
        const int g   = rem >> 4;
        const int c4  = rem & 15;
        const int k   = kbase + kk;            // always < 336
        const int j   = g * HH + (pass << 6) + (c4 << 2);
        float4 v;
        if (k < DIN) v = *(const float4*)(Wi + (size_t)k * G4 + j);
        else         v = *(const float4*)(Wh + (size_t)(k - DIN) * G4 + j);
        *(float4*)(dst + kk * 256 + g * 64 + (c4 << 2)) = v;
    }
}

// MLP panel: rows [kbase, kbase+56) of Wl [256x256]; zero-pad k >= 256.
__device__ __forceinline__ void load_mlp_panel(
    float* __restrict__ dst, const float* __restrict__ Wl, int kbase, int tid)
{
    #pragma unroll 2
    for (int it = 0; it < 14; ++it) {
        const int f  = tid + it * NTH;
        const int kk = f >> 6;
        const int c4 = f & 63;
        const int k  = kbase + kk;
        float4 v = make_float4(0.f, 0.f, 0.f, 0.f);
        if (k < HH) v = *(const float4*)(Wl + (size_t)k * HH + (c4 << 2));
        *(float4*)(dst + kk * 256 + (c4 << 2)) = v;
    }
}

// Output panel: rows [kbase, kbase+56) of Wout [256x64]; zero-pad.
__device__ __forceinline__ void load_out_panel(
    float* __restrict__ dst, const float* __restrict__ Wout, int kbase, int tid)
{
    #pragma unroll 2
    for (int it = 0; it < 4; ++it) {           // 896 float4
        const int f = tid + it * NTH;
        if (f < KP * 16) {
            const int kk = f >> 4;
            const int c4 = f & 15;
            const int k  = kbase + kk;
            float4 v = make_float4(0.f, 0.f, 0.f, 0.f);
            if (k < HH) v = *(const float4*)(Wout + (size_t)k * OUTD + (c4 << 2));
            *(float4*)(dst + kk * 64 + (c4 << 2)) = v;
        }
    }
}

__device__ __forceinline__ void gatef(float zi, float zf, float zg, float zo,
                                      float &c, float* __restrict__ sHN,
                                      int hk, int row)
{
    const float ig = sigf(zi);
    const float fg = sigf(zf);
    const float gg = zg * sigf(zg);       // silu
    const float og = sigf(zo);
    const float cn = fg * c + ig * gg;
    c = cn;
    sHN[hk * SAS + row] = og * cn * sigf(cn);  // o * silu(c_new)
}

__global__ void __launch_bounds__(NTH, 1)
lstm_fwd_kernel(const float* __restrict__ traj, const float* __restrict__ act,
                const float* __restrict__ Wi,   const float* __restrict__ Wh,
                const float* __restrict__ bh,   const float* __restrict__ mlpW,
                const float* __restrict__ mlpB, const float* __restrict__ Wout,
                const float* __restrict__ bout, float* __restrict__ out)
{
    extern __shared__ float sm[];
    float* sA  = sm + OFF_SA;    // [AROWS][36]  k-major: 0..79 x, 80..335 h, 336..359 zero
    float* sW  = sm + OFF_SW;    // [2][56][256]
    float* sHN = sm + OFF_SHN;   // [256][36]
    float* sB  = sm + OFF_SB;    // [1024]

    const int tid  = threadIdx.x;
    const int row0 = blockIdx.x * RPB;
    const int rgrp = tid & 7;
    const int cgrp = tid >> 3;       // 0..31
    const int r0   = rgrp << 2;

    // cell state in registers: creg[pass*8 + c*4 + r]
    float creg[32];
    #pragma unroll
    for (int i = 0; i < 32; ++i) creg[i] = 0.0f;

    // init: zero h+pad region of sA, cache bh
    for (int i = tid; i < (AROWS - DIN) * SAS; i += NTH) sA[DIN * SAS + i] = 0.0f;
    for (int i = tid; i < G4; i += NTH) sB[i] = bh[i];
    __syncthreads();

    // ============================ LSTM over time ============================
    for (int t = 0; t < TT; ++t) {
        for (int i = tid; i < DIN * RPB; i += NTH) {
            const int r = i & 31;
            const int k = i >> 5;
            const int row = row0 + r;
            float v;
            if (k < OBS) v = traj[((size_t)row * TT + t) * OBS + k];
            else         v = act [((size_t)row * TT + t) * ACTD + (k - OBS)];
            sA[k * SAS + r] = v;
        }
        __syncthreads();

        #pragma unroll
        for (int pass = 0; pass < 4; ++pass) {
            ull acc2[16];                       // [g][r] packed (col c0,c1)
            #pragma unroll
            for (int i = 0; i < 16; ++i) acc2[i] = 0ull;

            load_lstm_panel(sW, Wi, Wh, 0, pass, tid);
            __syncthreads();
            int buf = 0;
            for (int pi = 0; pi < NP_LSTM; ++pi) {
                if (pi + 1 < NP_LSTM)
                    load_lstm_panel(sW + (buf ^ 1) * (KP * 256), Wi, Wh,
                                    (pi + 1) * KP, pass, tid);
                const float* wp = sW + buf * (KP * 256);
                const int kb = pi * KP;
                #pragma unroll 4
                for (int kk = 0; kk < KP; ++kk) {
                    const float4 a = *(const float4*)(sA + (kb + kk) * SAS + r0);
                    const ull a0 = pk2(a.x, a.x), a1 = pk2(a.y, a.y);
                    const ull a2 = pk2(a.z, a.z), a3 = pk2(a.w, a.w);
                    const float* wr = wp + kk * 256 + (cgrp << 1);
                    #pragma unroll
                    for (int g = 0; g < 4; ++g) {
                        const ull w = *(const ull*)(wr + (g << 6));
                        ffma2(acc2[g * 4 + 0], w, a0);
                        ffma2(acc2[g * 4 + 1], w, a1);
                        ffma2(acc2[g * 4 + 2], w, a2);
                        ffma2(acc2[g * 4 + 3], w, a3);
                    }
                }
                __syncthreads();
                buf ^= 1;
            }

            // gate epilogue (exclusive ownership of (row,hk) pairs)
            const int hk0 = (pass << 6) + (cgrp << 1);
            const float bi0 = sB[hk0],       bi1 = sB[hk0 + 1];
            const float bf0 = sB[256 + hk0], bf1 = sB[256 + hk0 + 1];
            const float bg0 = sB[512 + hk0], bg1 = sB[512 + hk0 + 1];
            const float bo0 = sB[768 + hk0], bo1 = sB[768 + hk0 + 1];
            #pragma unroll
            for (int r = 0; r < 4; ++r) {
                float zi0, zi1, zf0, zf1, zg0, zg1, zo0, zo1;
                upk2(acc2[0  + r], zi0, zi1);
                upk2(acc2[4  + r], zf0, zf1);
                upk2(acc2[8  + r], zg0, zg1);
                upk2(acc2[12 + r], zo0, zo1);
                gatef(zi0 + bi0, zf0 + bf0, zg0 + bg0, zo0 + bo0,
                      creg[pass * 8 + 0 + r], sHN, hk0,     r0 + r);
                gatef(zi1 + bi1, zf1 + bf1, zg1 + bg1, zo1 + bo1,
                      creg[pass * 8 + 4 + r], sHN, hk0 + 1, r0 + r);
            }
        }
        __syncthreads();
        // commit h_new -> sA rows 80..335 (float4 over rows)
        for (int i = tid; i < HH * 8; i += NTH) {
            const int c = i >> 3, r4 = (i & 7) << 2;
            *(float4*)(sA + (DIN + c) * SAS + r4) = *(const float4*)(sHN + c * SAS + r4);
        }
        __syncthreads();
    }

    // ============================ MLP head ============================
    for (int l = 0; l < NL; ++l) {
        ull acc2[16];                           // [cpair][r]
        #pragma unroll
        for (int i = 0; i < 16; ++i) acc2[i] = 0ull;

        const float* Wl = mlpW + (size_t)l * HH * HH;
        load_mlp_panel(sW, Wl, 0, tid);
        __syncthreads();
        int buf = 0;
        for (int pi = 0; pi < NP_MLP; ++pi) {
            if (pi + 1 < NP_MLP)
                load_mlp_panel(sW + (buf ^ 1) * (KP * 256), Wl, (pi + 1) * KP, tid);
            const float* wp = sW + buf * (KP * 256);
            const int kb = pi * KP;
            #pragma unroll 4
            for (int kk = 0; kk < KP; ++kk) {
                const float4 a = *(const float4*)(sA + (DIN + kb + kk) * SAS + r0);
                const ull a0 = pk2(a.x, a.x), a1 = pk2(a.y, a.y);
                const ull a2 = pk2(a.z, a.z), a3 = pk2(a.w, a.w);
                const float* wr = wp + kk * 256 + (cgrp << 3);
                #pragma unroll
                for (int cp = 0; cp < 4; ++cp) {
                    const ull w = *(const ull*)(wr + (cp << 1));
                    ffma2(acc2[cp * 4 + 0], w, a0);
                    ffma2(acc2[cp * 4 + 1], w, a1);
                    ffma2(acc2[cp * 4 + 2], w, a2);
                    ffma2(acc2[cp * 4 + 3], w, a3);
                }
            }
            __syncthreads();
            buf ^= 1;
        }
        // silu epilogue -> sHN
        #pragma unroll
        for (int cp = 0; cp < 4; ++cp) {
            const int c0 = (cgrp << 3) + (cp << 1);
            const float b0 = mlpB[l * HH + c0];
            const float b1 = mlpB[l * HH + c0 + 1];
            #pragma unroll
            for (int r = 0; r < 4; ++r) {
                float v0, v1;
                upk2(acc2[cp * 4 + r], v0, v1);
                v0 += b0; v1 += b1;
                sHN[c0 * SAS + r0 + r]       = v0 * sigf(v0);
                sHN[(c0 + 1) * SAS + r0 + r] = v1 * sigf(v1);
            }
        }
        __syncthreads();
        for (int i = tid; i < HH * 8; i += NTH) {
            const int c = i >> 3, r4 = (i & 7) << 2;
            *(float4*)(sA + (DIN + c) * SAS + r4) = *(const float4*)(sHN + c * SAS + r4);
        }
        __syncthreads();
    }

    // ---- output layer: [32x256] @ [256x64] + bout
    {
        ull acc2o[4];
        #pragma unroll
        for (int i = 0; i < 4; ++i) acc2o[i] = 0ull;

        load_out_panel(sW, Wout, 0, tid);
        __syncthreads();
        int buf = 0;
        for (int pi = 0; pi < NP_MLP; ++pi) {
            if (pi + 1 < NP_MLP)
                load_out_panel(sW + (buf ^ 1) * (KP * 64), Wout, (pi + 1) * KP, tid);
            const float* wp = sW + buf * (KP * 64);
            const int kb = pi * KP;
            #pragma unroll 4
            for (int kk = 0; kk < KP; ++kk) {
                const float4 a = *(const float4*)(sA + (DIN + kb + kk) * SAS + r0);
                const ull w = *(const ull*)(wp + kk * 64 + (cgrp << 1));
                ffma2(acc2o[0], w, pk2(a.x, a.x));
                ffma2(acc2o[1], w, pk2(a.y, a.y));
                ffma2(acc2o[2], w, pk2(a.z, a.z));
                ffma2(acc2o[3], w, pk2(a.w, a.w));
            }
            __syncthreads();
            buf ^= 1;
        }
        const int c0 = cgrp << 1;
        const float b0 = bout[c0], b1 = bout[c0 + 1];
        #pragma unroll
        for (int r = 0; r < 4; ++r) {
            float v0, v1;
            upk2(acc2o[r], v0, v1);
            out[(size_t)(row0 + r0 + r) * OUTD + c0]     = v0 + b0;
            out[(size_t)(row0 + r0 + r) * OUTD + c0 + 1] = v1 + b1;
        }
    }
}

extern "C" void kernel_launch(void* const* d_in, const int* in_sizes, int n_in,
                              void* d_out, int out_size)
{
    const float* traj = (const float*)d_in[0];
    const float* act  = (const float*)d_in[1];
    const float* Wi   = (const float*)d_in[2];
    const float* Wh   = (const float*)d_in[3];
    const float* bh   = (const float*)d_in[4];
    const float* mlpW = (const float*)d_in[5];
    const float* mlpB = (const float*)d_in[6];
    const float* Wout = (const float*)d_in[7];
    const float* bout = (const float*)d_in[8];
    float* out = (float*)d_out;

    cudaFuncSetAttribute(lstm_fwd_kernel,
                         cudaFuncAttributeMaxDynamicSharedMemorySize,
                         SMEM_FLOATS * (int)sizeof(float));
    lstm_fwd_kernel<<<NCTA, NTH, SMEM_FLOATS * sizeof(float)>>>(
        traj, act, Wi, Wh, bh, mlpW, mlpB, Wout, bout, out);
}

// round 3
// speedup vs baseline: 4.1708x; 1.3198x over previous
#include <cuda_runtime.h>

// Problem constants
#define BB   4096
#define TT   50
#define OBS  64
#define ACTD 16
#define DIN  80      // OBS + ACT
#define HH   256
#define G4   1024    // 4*H
#define NL   5
#define OUTD 64

// Kernel config
#define RPB  32            // batch rows per CTA
#define NCTA (BB / RPB)    // 128
#define NTH  512
#define SAS  36            // sA row stride in floats
#define AROWS 336          // 80 x-rows + 256 h-rows (exact, no pad)

// Shared memory (floats)
#define SZ_SA   (AROWS * SAS)    // 12096
#define SZ_SHN  (HH * SAS)       //  9216
#define SZ_SB   (G4)             //  1024
#define OFF_SA  0
#define OFF_SHN (OFF_SA + SZ_SA)
#define OFF_SB  (OFF_SHN + SZ_SHN)
#define SMEM_FLOATS (OFF_SB + SZ_SB)   // 22336 floats = 89344 B

typedef unsigned long long ull;

__device__ __forceinline__ float sigf(float x) {
    return __fdividef(1.0f, 1.0f + __expf(-x));
}

// packed f32x2 (sm_103a FFMA2 — PTX-only path)
__device__ __forceinline__ void ffma2(ull &d, ull a, ull b) {
    asm("fma.rn.f32x2 %0, %1, %2, %0;" : "+l"(d) : "l"(a), "l"(b));
}
__device__ __forceinline__ ull pk2(float lo, float hi) {
    ull r; asm("mov.b64 %0, {%1, %2};" : "=l"(r) : "f"(lo), "f"(hi)); return r;
}
__device__ __forceinline__ void upk2(ull v, float &lo, float &hi) {
    asm("mov.b64 {%0, %1}, %2;" : "=f"(lo), "=f"(hi) : "l"(v));
}

__device__ __forceinline__ void gatef(float zi, float zf, float zg, float zo,
                                      float &c, float* __restrict__ sHN,
                                      int hk, int row)
{
    const float ig = sigf(zi);
    const float fg = sigf(zf);
    const float gg = zg * sigf(zg);       // silu
    const float og = sigf(zo);
    const float cn = fg * c + ig * gg;
    c = cn;
    sHN[hk * SAS + row] = og * cn * sigf(cn);  // o * silu(c_new)
}

__global__ void __launch_bounds__(NTH, 1)
lstm_fwd_kernel(const float* __restrict__ traj, const float* __restrict__ act,
                const float* __restrict__ Wi,   const float* __restrict__ Wh,
                const float* __restrict__ bh,   const float* __restrict__ mlpW,
                const float* __restrict__ mlpB, const float* __restrict__ Wout,
                const float* __restrict__ bout, float* __restrict__ out)
{
    extern __shared__ float sm[];
    float* sA  = sm + OFF_SA;    // [336][36] k-major: 0..79 x, 80..335 h (or MLP act)
    float* sHN = sm + OFF_SHN;   // [256][36]
    float* sB  = sm + OFF_SB;    // [1024]

    const int tid  = threadIdx.x;
    const int row0 = blockIdx.x * RPB;
    const int rgrp = tid & 7;
    const int cgrp = tid >> 3;       // 0..63
    const int r0   = rgrp << 2;

    // cell state in registers: creg[half*8 + c*4 + r]
    float creg[16];
    #pragma unroll
    for (int i = 0; i < 16; ++i) creg[i] = 0.0f;

    // init: zero h region of sA, cache bh, preload x(0)
    for (int i = tid; i < HH * SAS; i += NTH) sA[DIN * SAS + i] = 0.0f;
    for (int i = tid; i < G4; i += NTH) sB[i] = bh[i];
    for (int i = tid; i < DIN * RPB; i += NTH) {
        const int r = i & 31, k = i >> 5;
        const int row = row0 + r;
        float v;
        if (k < OBS) v = traj[((size_t)row * TT) * OBS + k];
        else         v = act [((size_t)row * TT) * ACTD + (k - OBS)];
        sA[k * SAS + r] = v;
    }
    __syncthreads();

    // ============================ LSTM over time ============================
    for (int t = 0; t < TT; ++t) {
        #pragma unroll
        for (int half = 0; half < 2; ++half) {
            const int hk0 = (half << 7) + (cgrp << 1);
            const float* wI = Wi + hk0;    // + k*1024 + g*256
            const float* wH = Wh + hk0;

            ull acc2[16];                  // [g][r], packed col pair
            #pragma unroll
            for (int i = 0; i < 16; ++i) acc2[i] = 0ull;

            // x part: k = 0..79
            #pragma unroll 4
            for (int k = 0; k < DIN; ++k) {
                const float4 a = *(const float4*)(sA + k * SAS + r0);
                const ull a0 = pk2(a.x, a.x), a1 = pk2(a.y, a.y);
                const ull a2 = pk2(a.z, a.z), a3 = pk2(a.w, a.w);
                const float* wr = wI + (size_t)k * G4;
                #pragma unroll
                for (int g = 0; g < 4; ++g) {
                    const ull w = *(const ull*)(wr + (g << 8));
                    ffma2(acc2[g * 4 + 0], w, a0);
                    ffma2(acc2[g * 4 + 1], w, a1);
                    ffma2(acc2[g * 4 + 2], w, a2);
                    ffma2(acc2[g * 4 + 3], w, a3);
                }
            }
            // h part: k = 0..255
            #pragma unroll 4
            for (int k = 0; k < HH; ++k) {
                const float4 a = *(const float4*)(sA + (DIN + k) * SAS + r0);
                const ull a0 = pk2(a.x, a.x), a1 = pk2(a.y, a.y);
                const ull a2 = pk2(a.z, a.z), a3 = pk2(a.w, a.w);
                const float* wr = wH + (size_t)k * G4;
                #pragma unroll
                for (int g = 0; g < 4; ++g) {
                    const ull w = *(const ull*)(wr + (g << 8));
                    ffma2(acc2[g * 4 + 0], w, a0);
                    ffma2(acc2[g * 4 + 1], w, a1);
                    ffma2(acc2[g * 4 + 2], w, a2);
                    ffma2(acc2[g * 4 + 3], w, a3);
                }
            }

            // gate epilogue — thread exclusively owns (row, hk0..hk0+1)
            const float bi0 = sB[hk0],       bi1 = sB[hk0 + 1];
            const float bf0 = sB[256 + hk0], bf1 = sB[256 + hk0 + 1];
            const float bg0 = sB[512 + hk0], bg1 = sB[512 + hk0 + 1];
            const float bo0 = sB[768 + hk0], bo1 = sB[768 + hk0 + 1];
            #pragma unroll
            for (int r = 0; r < 4; ++r) {
                float zi0, zi1, zf0, zf1, zg0, zg1, zo0, zo1;
                upk2(acc2[0  + r], zi0, zi1);
                upk2(acc2[4  + r], zf0, zf1);
                upk2(acc2[8  + r], zg0, zg1);
                upk2(acc2[12 + r], zo0, zo1);
                gatef(zi0 + bi0, zf0 + bf0, zg0 + bg0, zo0 + bo0,
                      creg[half * 8 + 0 + r], sHN, hk0,     r0 + r);
                gatef(zi1 + bi1, zf1 + bf1, zg1 + bg1, zo1 + bo1,
                      creg[half * 8 + 4 + r], sHN, hk0 + 1, r0 + r);
            }
        }
        __syncthreads();

        // commit h_new -> sA h rows; preload x(t+1)
        for (int i = tid; i < HH * 8; i += NTH) {
            const int c = i >> 3, r4 = (i & 7) << 2;
            *(float4*)(sA + (DIN + c) * SAS + r4) = *(const float4*)(sHN + c * SAS + r4);
        }
        if (t + 1 < TT) {
            for (int i = tid; i < DIN * RPB; i += NTH) {
                const int r = i & 31, k = i >> 5;
                const int row = row0 + r;
                float v;
                if (k < OBS) v = traj[((size_t)row * TT + t + 1) * OBS + k];
                else         v = act [((size_t)row * TT + t + 1) * ACTD + (k - OBS)];
                sA[k * SAS + r] = v;
            }
        }
        __syncthreads();
    }

    // ============================ MLP head ============================
    // Each thread: 4 rows x 4 cols (cols = cgrp*4, one LDG.128 per kk).
    for (int l = 0; l < NL; ++l) {
        const float* Wl = mlpW + (size_t)l * HH * HH + (cgrp << 2);
        ull acc2[8];                          // [pair][r]
        #pragma unroll
        for (int i = 0; i < 8; ++i) acc2[i] = 0ull;

        #pragma unroll 4
        for (int k = 0; k < HH; ++k) {
            const float4 a = *(const float4*)(sA + (DIN + k) * SAS + r0);
            const ull a0 = pk2(a.x, a.x), a1 = pk2(a.y, a.y);
            const ull a2 = pk2(a.z, a.z), a3 = pk2(a.w, a.w);
            const float4 w4 = *(const float4*)(Wl + (size_t)k * HH);
            const ull w01 = pk2(w4.x, w4.y);
            const ull w23 = pk2(w4.z, w4.w);
            ffma2(acc2[0], w01, a0);  ffma2(acc2[1], w01, a1);
            ffma2(acc2[2], w01, a2);  ffma2(acc2[3], w01, a3);
            ffma2(acc2[4], w23, a0);  ffma2(acc2[5], w23, a1);
            ffma2(acc2[6], w23, a2);  ffma2(acc2[7], w23, a3);
        }
        __syncthreads();   // all reads of sA done before overwrite
        // silu epilogue -> sHN
        const int c0 = cgrp << 2;
        const float b0 = mlpB[l * HH + c0],     b1 = mlpB[l * HH + c0 + 1];
        const float b2 = mlpB[l * HH + c0 + 2], b3 = mlpB[l * HH + c0 + 3];
        #pragma unroll
        for (int r = 0; r < 4; ++r) {
            float v0, v1, v2, v3;
            upk2(acc2[0 + r], v0, v1);
            upk2(acc2[4 + r], v2, v3);
            v0 += b0; v1 += b1; v2 += b2; v3 += b3;
            sHN[(c0 + 0) * SAS + r0 + r] = v0 * sigf(v0);
            sHN[(c0 + 1) * SAS + r0 + r] = v1 * sigf(v1);
            sHN[(c0 + 2) * SAS + r0 + r] = v2 * sigf(v2);
            sHN[(c0 + 3) * SAS + r0 + r] = v3 * sigf(v3);
        }
        __syncthreads();
        for (int i = tid; i < HH * 8; i += NTH) {
            const int c = i >> 3, r4 = (i & 7) << 2;
            *(float4*)(sA + (DIN + c) * SAS + r4) = *(const float4*)(sHN + c * SAS + r4);
        }
        __syncthreads();
    }

    // ---- output layer: [32x256] @ [256x64] + bout, K split across cgrp>>5
    {
        const int cp    = cgrp & 31;       // col pair 0..31
        const int khalf = cgrp >> 5;       // 0 or 1
        const int c0    = cp << 1;
        const float* Wo = Wout + c0;

        ull acc2o[4];
        #pragma unroll
        for (int i = 0; i < 4; ++i) acc2o[i] = 0ull;

        const int kb = khalf << 7;         // 0 or 128
        #pragma unroll 4
        for (int k = 0; k < 128; ++k) {
            const float4 a = *(const float4*)(sA + (DIN + kb + k) * SAS + r0);
            const ull w = *(const ull*)(Wo + (size_t)(kb + k) * OUTD);
            ffma2(acc2o[0], w, pk2(a.x, a.x));
            ffma2(acc2o[1], w, pk2(a.y, a.y));
            ffma2(acc2o[2], w, pk2(a.z, a.z));
            ffma2(acc2o[3], w, pk2(a.w, a.w));
        }
        __syncthreads();
        // khalf=1 threads park partials in sHN, khalf=0 adds + writes out
        if (khalf == 1) {
            #pragma unroll
            for (int r = 0; r < 4; ++r) {
                float v0, v1; upk2(acc2o[r], v0, v1);
                sHN[(c0 + 0) * SAS + r0 + r] = v0;
                sHN[(c0 + 1) * SAS + r0 + r] = v1;
            }
        }
        __syncthreads();
        if (khalf == 0) {
            const float b0 = bout[c0], b1 = bout[c0 + 1];
            #pragma unroll
            for (int r = 0; r < 4; ++r) {
                float v0, v1; upk2(acc2o[r], v0, v1);
                v0 += sHN[(c0 + 0) * SAS + r0 + r] + b0;
                v1 += sHN[(c0 + 1) * SAS + r0 + r] + b1;
                out[(size_t)(row0 + r0 + r) * OUTD + c0]     = v0;
                out[(size_t)(row0 + r0 + r) * OUTD + c0 + 1] = v1;
            }
        }
    }
}

extern "C" void kernel_launch(void* const* d_in, const int* in_sizes, int n_in,
                              void* d_out, int out_size)
{
    const float* traj = (const float*)d_in[0];
    const float* act  = (const float*)d_in[1];
    const float* Wi   = (const float*)d_in[2];
    const float* Wh   = (const float*)d_in[3];
    const float* bh   = (const float*)d_in[4];
    const float* mlpW = (const float*)d_in[5];
    const float* mlpB = (const float*)d_in[6];
    const float* Wout = (const float*)d_in[7];
    const float* bout = (const float*)d_in[8];
    float* out = (float*)d_out;

    cudaFuncSetAttribute(lstm_fwd_kernel,
                         cudaFuncAttributeMaxDynamicSharedMemorySize,
                         SMEM_FLOATS * (int)sizeof(float));
    lstm_fwd_kernel<<<NCTA, NTH, SMEM_FLOATS * sizeof(float)>>>(
        traj, act, Wi, Wh, bh, mlpW, mlpB, Wout, bout, out);
}